// round 2
// baseline (speedup 1.0000x reference)
#include <cuda_runtime.h>
#include <cuda_bf16.h>
#include <math.h>

#define B 8
#define A 120000
#define C 80
#define TOPN 1000
#define MAXDET 100
#define CANDMAX 4096
#define NBIN 65536

// ---------------- scratch (device globals; no allocation allowed) ----------------
__device__ int                g_histc[B * NBIN + B];   // [0,B*NBIN): hist, then B counters
__device__ float              g_scores[B * A];
__device__ unsigned char      g_classes[B * A];
__device__ int                g_P[B];
__device__ unsigned long long g_cand[B * CANDMAX];

__device__ __forceinline__ int hbin(unsigned bits) {
    int h = ((int)bits - 0x3F000000) >> 7;   // 128-ULP bins over [0.5, 1.0)
    h = h < 0 ? 0 : h;
    h = h > (NBIN - 1) ? (NBIN - 1) : h;
    return h;
}

// ---------------- K1: max/argmax over 80 classes + global 64K-bin histogram ----------------
__global__ void __launch_bounds__(256) k_scores(const float* __restrict__ cls) {
    int img = blockIdx.y;
    int a   = blockIdx.x * 256 + threadIdx.x;
    if (a >= A) return;
    const float4* p = (const float4*)(cls + ((size_t)img * A + a) * C);
    float best = -1e30f; int bi = 0;
#pragma unroll
    for (int i = 0; i < C / 4; i++) {
        float4 v = p[i];
        if (v.x > best) { best = v.x; bi = 4 * i + 0; }
        if (v.y > best) { best = v.y; bi = 4 * i + 1; }
        if (v.z > best) { best = v.z; bi = 4 * i + 2; }
        if (v.w > best) { best = v.w; bi = 4 * i + 3; }
    }
    g_scores[img * A + a]  = best;
    g_classes[img * A + a] = (unsigned char)bi;
    atomicAdd(&g_histc[img * NBIN + hbin(__float_as_uint(best))], 1);
}

// ---------------- K2: top-down scan of 64K bins -> exact bin threshold P ----------------
__global__ void __launch_bounds__(1024) k_scan() {
    int img = blockIdx.x, t = threadIdx.x;
    __shared__ int ps[1024];
    const int* hh = g_histc + img * NBIN;
    int s = 0;
#pragma unroll 8
    for (int j = 0; j < 64; j++) s += hh[NBIN - 1 - (t * 64 + j)];
    ps[t] = s;
    __syncthreads();
    for (int off = 1; off < 1024; off <<= 1) {
        int tv = (t >= off) ? ps[t - off] : 0;
        __syncthreads();
        ps[t] += tv;
        __syncthreads();
    }
    int cum = ps[t] - s;           // exclusive (bins strictly above this thread's chunk)
    if (!(cum < TOPN && cum + s >= TOPN)) return;  // crossing not in my chunk
    for (int j = 0; j < 64; j++) {
        int v = hh[NBIN - 1 - (t * 64 + j)];
        cum += v;
        if (cum >= TOPN && cum - v < TOPN) { g_P[img] = NBIN - 1 - (t * 64 + j); return; }
    }
}

// ---------------- K3: compact candidates (hbin >= P) ----------------
__global__ void __launch_bounds__(256) k_compact() {
    int img = blockIdx.y;
    int i   = blockIdx.x * 256 + threadIdx.x;
    if (i >= A) return;
    unsigned bits = __float_as_uint(g_scores[img * A + i]);
    if (hbin(bits) >= g_P[img]) {
        int pos = atomicAdd(&g_histc[B * NBIN + img], 1);
        if (pos < CANDMAX)
            g_cand[img * CANDMAX + pos] =
                ((unsigned long long)bits << 32) | (unsigned)(~(unsigned)i);
    }
}

// ---------------- K4: fused rank-sort + decode + IoU mask + serial NMS + output ----------------
#define POST_SMEM (131072 + 16384 + 4096 + 4096 + 4096 + 1024)

__global__ void __launch_bounds__(1024) k_post(const float* __restrict__ reg,
                                               const float* __restrict__ anc,
                                               float* __restrict__ out) {
    int img = blockIdx.x, tid = threadIdx.x;
    extern __shared__ char sm[];
    unsigned long long* keys  = (unsigned long long*)sm;        // 4096 u64 (32KB, dies)
    unsigned*           s_mask = (unsigned*)sm;                 // 32768 words (128KB, aliases keys)
    float4* sb   = (float4*)(sm + 131072);                      // 1024 boxes
    float*  sa   = (float*)(sm + 131072 + 16384);               // areas
    float*  ssc  = sa + 1024;                                   // scores
    int*    scls = (int*)(ssc + 1024);                          // classes
    unsigned* s_val  = (unsigned*)(scls + 1024);                // 32
    unsigned* s_keep = s_val + 32;                              // 32
    int*      s_kept = (int*)(s_keep + 32);                     // 100
    int*      s_nk   = s_kept + MAXDET;                         // 1

    int cnt = g_histc[B * NBIN + img];
    if (cnt > CANDMAX) cnt = CANDMAX;
    for (int i = tid; i < cnt; i += 1024) keys[i] = g_cand[img * CANDMAX + i];
    if (tid < 1024 - TOPN) {   // init pad slots 1000..1023
        int r = TOPN + tid;
        ssc[r] = -1.0f; sa[r] = 0.0f; scls[r] = -1;
        sb[r]  = make_float4(0.f, 0.f, 0.f, 0.f);
    }
    __syncthreads();

    // rank sort (keys unique -> exact rank); winners decode directly into slot r
    for (int i = tid; i < cnt; i += 1024) {
        unsigned long long k = keys[i];
        int r = 0;
#pragma unroll 8
        for (int j = 0; j < cnt; j++) r += (keys[j] > k);
        if (r < TOPN) {
            unsigned bits = (unsigned)(k >> 32);
            int idx = (int)(~(unsigned)(k & 0xffffffffu));
            size_t gi = (size_t)img * A + idx;
            float4 r4 = __ldg((const float4*)reg + gi);
            float4 a4 = __ldg((const float4*)anc + gi);
            float aw  = __fsub_rn(a4.z, a4.x);
            float ah  = __fsub_rn(a4.w, a4.y);
            float acx = __fadd_rn(a4.x, __fmul_rn(0.5f, aw));
            float acy = __fadd_rn(a4.y, __fmul_rn(0.5f, ah));
            float r0 = __fmul_rn(r4.x, 0.1f);
            float r1 = __fmul_rn(r4.y, 0.1f);
            float r2 = __fmul_rn(r4.z, 0.2f);
            float r3 = __fmul_rn(r4.w, 0.2f);
            float pw  = __fmul_rn(expf(r2), aw);
            float ph  = __fmul_rn(expf(r3), ah);
            float pcx = __fadd_rn(__fmul_rn(r0, aw), acx);
            float pcy = __fadd_rn(__fmul_rn(r1, ah), acy);
            float x1 = truncf(__fsub_rn(pcx, __fmul_rn(0.5f, pw)));
            float y1 = truncf(__fsub_rn(pcy, __fmul_rn(0.5f, ph)));
            float x2 = truncf(__fadd_rn(pcx, __fmul_rn(0.5f, pw)));
            float y2 = truncf(__fadd_rn(pcy, __fmul_rn(0.5f, ph)));
            x1 = fmaxf(x1, 0.0f);
            y1 = fmaxf(y1, 0.0f);
            x2 = fminf(x2, 639.0f);
            y2 = fminf(y2, 639.0f);
            ssc[r]  = __uint_as_float(bits);
            scls[r] = (int)g_classes[gi];
            sb[r]   = make_float4(x1, y1, x2, y2);
            sa[r]   = __fmul_rn(__fsub_rn(x2, x1), __fsub_rn(y2, y1));
        }
    }
    __syncthreads();

    // zero mask region (overwrites dead keys)
    for (int i = tid; i < 32768; i += 1024) s_mask[i] = 0;
    __syncthreads();

    // upper-triangle suppression mask; warp w owns rows {w, w+32, ...} (balanced)
    int warp = tid >> 5, lane = tid & 31;
    for (int kk = 0; kk < 32; kk++) {
        int i = kk * 32 + warp;
        float4 bi = sb[i];
        float  ai = sa[i];
        for (int it = kk; it < 32; it++) {
            int j = it * 32 + lane;
            bool supp = false;
            if (i < TOPN && j < TOPN && j > i) {
                float4 bj = sb[j];
                float ltx = fmaxf(bi.x, bj.x), lty = fmaxf(bi.y, bj.y);
                float rbx = fminf(bi.z, bj.z), rby = fminf(bi.w, bj.w);
                float w = fmaxf(__fsub_rn(rbx, ltx), 0.0f);
                float h = fmaxf(__fsub_rn(rby, lty), 0.0f);
                float inter = __fmul_rn(w, h);
                float s   = __fadd_rn(ai, sa[j]);
                float uni = __fsub_rn(s, inter);
                // exact equivalent of fl(inter/uni) > 0.5 on integer-valued fp32
                supp = (uni > 0.0f) ? (__fmul_rn(3.0f, inter) > s)
                                    : (uni == 0.0f && inter > 0.0f);
            }
            unsigned word = __ballot_sync(0xffffffffu, supp);
            if (lane == 0) s_mask[i * 32 + it] = word;
        }
    }
    __syncthreads();

    // validity bitmap
    for (int c = warp; c < 32; c += 32) {}  // (warps 0..31 each do one chunk below)
    {
        int c = warp;
        unsigned vm = __ballot_sync(0xffffffffu, ssc[c * 32 + lane] > 0.05f);
        if (lane == 0) s_val[c] = vm;
    }
    __syncthreads();

    // serial greedy NMS (warp 0): chunked bitmask scan
    if (warp == 0) {
        unsigned rem = 0;  // lane owns removed-bitmap word `lane`
        for (int c = 0; c < 32; c++) {
            unsigned remc = __shfl_sync(0xffffffffu, rem, c);
            unsigned vm = s_val[c];
            unsigned mcol[32];
#pragma unroll
            for (int b = 0; b < 32; b++) mcol[b] = s_mask[(c * 32 + b) * 32 + c];
            unsigned keep = 0;
#pragma unroll
            for (int b = 0; b < 32; b++) {
                if (((vm >> b) & 1u) && !((remc >> b) & 1u)) {
                    keep |= (1u << b);
                    remc |= mcol[b];
                }
            }
            unsigned mrow[32];
#pragma unroll
            for (int b = 0; b < 32; b++) mrow[b] = s_mask[(c * 32 + b) * 32 + lane];
#pragma unroll
            for (int b = 0; b < 32; b++)
                if ((keep >> b) & 1u) rem |= mrow[b];
            if (lane == 0) s_keep[c] = keep;
        }
        __syncwarp();
        unsigned kb = s_keep[lane];
        int pc = __popc(kb);
        int x = pc;
        for (int off = 1; off < 32; off <<= 1) {
            int y = __shfl_up_sync(0xffffffffu, x, off);
            if (lane >= off) x += y;
        }
        if (lane == 31) *s_nk = x;
        int off = x - pc;
        while (kb) {
            int b = __ffs(kb) - 1;
            kb &= kb - 1;
            if (off < MAXDET) s_kept[off] = lane * 32 + b;
            off++;
        }
    }
    __syncthreads();

    if (tid < MAXDET) {
        int nk = *s_nk;
        float so = -1.0f, co = -1.0f;
        float4 bo = make_float4(-1.0f, -1.0f, -1.0f, -1.0f);
        if (tid < nk) {
            int i = s_kept[tid];
            so = ssc[i];
            co = (float)scls[i];
            bo = sb[i];
        }
        out[img * MAXDET + tid]              = so;
        out[B * MAXDET + img * MAXDET + tid] = co;
        float* ob = out + 2 * B * MAXDET + (img * MAXDET + tid) * 4;
        ob[0] = bo.x; ob[1] = bo.y; ob[2] = bo.z; ob[3] = bo.w;
    }
}

// ---------------- launch ----------------
extern "C" void kernel_launch(void* const* d_in, const int* in_sizes, int n_in,
                              void* d_out, int out_size) {
    const float* cls = (const float*)d_in[0];
    const float* reg = (const float*)d_in[1];
    const float* anc = (const float*)d_in[2];
    float* out = (float*)d_out;
    (void)in_sizes; (void)n_in; (void)out_size;

    void* histPtr = nullptr;
    cudaGetSymbolAddress(&histPtr, g_histc);
    cudaFuncSetAttribute(k_post, cudaFuncAttributeMaxDynamicSharedMemorySize, POST_SMEM);

    const int GRID_A = (A + 255) / 256;  // 469
    cudaMemsetAsync(histPtr, 0, (size_t)(B * NBIN + B) * sizeof(int), 0);
    k_scores<<<dim3(GRID_A, B), 256>>>(cls);
    k_scan<<<B, 1024>>>();
    k_compact<<<dim3(GRID_A, B), 256>>>();
    k_post<<<B, 1024, POST_SMEM>>>(reg, anc, out);
}